// round 9
// baseline (speedup 1.0000x reference)
#include <cuda_runtime.h>
#include <math.h>

#define NB 32
#define NS 4096
#define ND 512
#define NCHUNK 32
#define ROWS_PER_CHUNK (NS / NCHUNK)        // 128
#define T1 128
#define BIGV 10000.0f

// packed partials: (sum, max, min, acc) per (batch, chunk, col) = 8.4 MB
__device__ float4   g_part[NB][NCHUNK][ND];
__device__ float    g_pm [NB][NCHUNK];
__device__ float    g_pl [NB][NCHUNK];
__device__ float    g_pcnt[NB][NCHUNK];
__device__ unsigned g_done[NB];   // zero-init; finisher resets -> deterministic per replay

__device__ __forceinline__ float dot4(const float4& a, const float4& b) {
    return a.x * b.x + a.y * b.y + a.z * b.z + a.w * b.w;
}

__global__ __launch_bounds__(T1) void pool_fused(
    const float* __restrict__ x,
    const int* __restrict__ mask,   // 4-byte mask (int32 {0,1} or f32 {0.,1.}): nonzero-bits test exact
    const float* __restrict__ w,
    float* __restrict__ out)
{
    const int chunk = blockIdx.x;
    const int b     = blockIdx.y;
    const int t     = threadIdx.x;
    const int lane  = t & 31;
    const int wid   = t >> 5;

    __shared__ int      s_list[ROWS_PER_CHUNK];
    __shared__ int      s_cnt4[4];
    __shared__ float    s_m[4], s_l[4], s_cnt[4];
    __shared__ float    s_mrg[2][4][ND];       // two planes, reused (16 KB)
    __shared__ unsigned s_isLast;
    __shared__ float    s_wc[NCHUNK];
    __shared__ float    s_invcnt;

    float4 w4[4];
    #pragma unroll
    for (int k = 0; k < 4; k++)
        w4[k] = *reinterpret_cast<const float4*>(w + k * 128 + lane * 4);

    float4 vsum[4], vmax[4], vmin[4], vacc[4];
    #pragma unroll
    for (int k = 0; k < 4; k++) {
        vsum[k] = make_float4(0.f, 0.f, 0.f, 0.f);
        vmax[k] = make_float4(-BIGV, -BIGV, -BIGV, -BIGV);
        vmin[k] = make_float4( BIGV,  BIGV,  BIGV,  BIGV);
        vacc[k] = make_float4(0.f, 0.f, 0.f, 0.f);
    }
    float m = -1e30f, l = 0.f, cnt = 0.f;

    const int rowbase = chunk * ROWS_PER_CHUNK;
    const float* xb = x + (size_t)b * NS * ND;

    // ---- block-level compaction of 128 rows (balanced 4-way split)
    const int  myrow = wid * 32 + lane;
    const bool a = (mask[(size_t)b * NS + rowbase + myrow] != 0);
    const unsigned bal = __ballot_sync(0xffffffffu, a);
    if (lane == 0) s_cnt4[wid] = __popc(bal);
    __syncthreads();
    int off = 0;
    #pragma unroll
    for (int wv = 0; wv < 4; wv++) if (wv < wid) off += s_cnt4[wv];
    const int ntot = s_cnt4[0] + s_cnt4[1] + s_cnt4[2] + s_cnt4[3];
    if (a) s_list[off + __popc(bal & ((1u << lane) - 1u))] = myrow;
    __syncthreads();

    const int per  = (ntot + 3) >> 2;
    const int ibeg = wid * per;
    const int iend = min(ibeg + per, ntot);

    // ---- dense main loop: 4 active rows / iteration, unconditional loads
    int i = ibeg;
    for (; i + 4 <= iend; i += 4) {
        float4 v[4][4];
        #pragma unroll
        for (int j = 0; j < 4; j++) {
            const float* p = xb + (size_t)(rowbase + s_list[i + j]) * ND + lane * 4;
            #pragma unroll
            for (int k = 0; k < 4; k++)
                v[j][k] = *reinterpret_cast<const float4*>(p + k * 128);
        }
        float d[4];
        #pragma unroll
        for (int j = 0; j < 4; j++)
            d[j] = dot4(v[j][0], w4[0]) + dot4(v[j][1], w4[1])
                 + dot4(v[j][2], w4[2]) + dot4(v[j][3], w4[3]);
        #pragma unroll
        for (int offs = 16; offs > 0; offs >>= 1) {
            #pragma unroll
            for (int j = 0; j < 4; j++)
                d[j] += __shfl_xor_sync(0xffffffffu, d[j], offs);
        }

        float newm = m;
        #pragma unroll
        for (int j = 0; j < 4; j++) newm = fmaxf(newm, d[j]);
        const float scale = __expf(m - newm);
        m = newm;
        l *= scale;
        float e[4];
        #pragma unroll
        for (int j = 0; j < 4; j++) { e[j] = __expf(d[j] - m); l += e[j]; }
        cnt += 4.f;

        #pragma unroll
        for (int k = 0; k < 4; k++) {
            float* A  = reinterpret_cast<float*>(&vacc[k]);
            float* S  = reinterpret_cast<float*>(&vsum[k]);
            float* Mx = reinterpret_cast<float*>(&vmax[k]);
            float* Mn = reinterpret_cast<float*>(&vmin[k]);
            #pragma unroll
            for (int c = 0; c < 4; c++) {
                const float x0 = reinterpret_cast<float*>(&v[0][k])[c];
                const float x1 = reinterpret_cast<float*>(&v[1][k])[c];
                const float x2 = reinterpret_cast<float*>(&v[2][k])[c];
                const float x3 = reinterpret_cast<float*>(&v[3][k])[c];
                A[c]  = A[c] * scale + e[0] * x0 + e[1] * x1 + e[2] * x2 + e[3] * x3;
                S[c] += (x0 + x1) + (x2 + x3);
                Mx[c] = fmaxf(Mx[c], fmaxf(fmaxf(x0, x1), fmaxf(x2, x3)));
                Mn[c] = fminf(Mn[c], fminf(fminf(x0, x1), fminf(x2, x3)));
            }
        }
    }
    for (; i < iend; i++) {   // tail
        const float* p = xb + (size_t)(rowbase + s_list[i]) * ND + lane * 4;
        float4 v0[4];
        #pragma unroll
        for (int k = 0; k < 4; k++) v0[k] = *reinterpret_cast<const float4*>(p + k * 128);
        float d0 = dot4(v0[0], w4[0]) + dot4(v0[1], w4[1])
                 + dot4(v0[2], w4[2]) + dot4(v0[3], w4[3]);
        #pragma unroll
        for (int offs = 16; offs > 0; offs >>= 1)
            d0 += __shfl_xor_sync(0xffffffffu, d0, offs);
        const float newm  = fmaxf(m, d0);
        const float scale = __expf(m - newm);
        m = newm;
        l *= scale;
        const float e0 = __expf(d0 - m);
        l += e0;
        cnt += 1.f;
        #pragma unroll
        for (int k = 0; k < 4; k++) {
            float* A  = reinterpret_cast<float*>(&vacc[k]);
            float* S  = reinterpret_cast<float*>(&vsum[k]);
            float* Mx = reinterpret_cast<float*>(&vmax[k]);
            float* Mn = reinterpret_cast<float*>(&vmin[k]);
            #pragma unroll
            for (int c = 0; c < 4; c++) {
                const float x0 = reinterpret_cast<float*>(&v0[k])[c];
                A[c]  = A[c] * scale + e0 * x0;
                S[c] += x0;
                Mx[c] = fmaxf(Mx[c], x0);
                Mn[c] = fminf(Mn[c], x0);
            }
        }
    }

    // ---- two-stage merge across 4 warps (smem plane reuse), packed float4 output
    if (lane == 0) { s_m[wid] = m; s_cnt[wid] = cnt; }
    #pragma unroll
    for (int k = 0; k < 4; k++) {
        const int c = k * 128 + lane * 4;
        *reinterpret_cast<float4*>(&s_mrg[0][wid][c]) = vsum[k];
        *reinterpret_cast<float4*>(&s_mrg[1][wid][c]) = vmax[k];
    }
    __syncthreads();

    const float M  = fmaxf(fmaxf(s_m[0], s_m[1]), fmaxf(s_m[2], s_m[3]));
    const float sc = __expf(m - M);

    const int c0 = t * 4;
    float4 osum = *reinterpret_cast<float4*>(&s_mrg[0][0][c0]);
    float4 omax = *reinterpret_cast<float4*>(&s_mrg[1][0][c0]);
    #pragma unroll
    for (int wi = 1; wi < 4; wi++) {
        const float4 q0 = *reinterpret_cast<float4*>(&s_mrg[0][wi][c0]);
        const float4 q1 = *reinterpret_cast<float4*>(&s_mrg[1][wi][c0]);
        osum.x += q0.x; osum.y += q0.y; osum.z += q0.z; osum.w += q0.w;
        omax.x = fmaxf(omax.x, q1.x); omax.y = fmaxf(omax.y, q1.y);
        omax.z = fmaxf(omax.z, q1.z); omax.w = fmaxf(omax.w, q1.w);
    }
    __syncthreads();   // protect plane reuse

    #pragma unroll
    for (int k = 0; k < 4; k++) {
        const int c = k * 128 + lane * 4;
        *reinterpret_cast<float4*>(&s_mrg[0][wid][c]) = vmin[k];
        float4 av = vacc[k];
        av.x *= sc; av.y *= sc; av.z *= sc; av.w *= sc;
        *reinterpret_cast<float4*>(&s_mrg[1][wid][c]) = av;
    }
    if (lane == 0) s_l[wid] = l * sc;
    __syncthreads();

    float4 omin = *reinterpret_cast<float4*>(&s_mrg[0][0][c0]);
    float4 oacc = *reinterpret_cast<float4*>(&s_mrg[1][0][c0]);
    #pragma unroll
    for (int wi = 1; wi < 4; wi++) {
        const float4 q0 = *reinterpret_cast<float4*>(&s_mrg[0][wi][c0]);
        const float4 q1 = *reinterpret_cast<float4*>(&s_mrg[1][wi][c0]);
        omin.x = fminf(omin.x, q0.x); omin.y = fminf(omin.y, q0.y);
        omin.z = fminf(omin.z, q0.z); omin.w = fminf(omin.w, q0.w);
        oacc.x += q1.x; oacc.y += q1.y; oacc.z += q1.z; oacc.w += q1.w;
    }

    {
        const float* su = reinterpret_cast<const float*>(&osum);
        const float* mx = reinterpret_cast<const float*>(&omax);
        const float* mn = reinterpret_cast<const float*>(&omin);
        const float* ac = reinterpret_cast<const float*>(&oacc);
        #pragma unroll
        for (int j = 0; j < 4; j++)
            g_part[b][chunk][c0 + j] = make_float4(su[j], mx[j], mn[j], ac[j]);
    }
    if (t == 0) {
        g_pm[b][chunk]   = M;
        g_pl[b][chunk]   = s_l[0] + s_l[1] + s_l[2] + s_l[3];
        g_pcnt[b][chunk] = s_cnt[0] + s_cnt[1] + s_cnt[2] + s_cnt[3];
    }

    // ---- last-CTA-per-batch finisher
    __threadfence();
    if (t == 0) {
        const unsigned prev = atomicAdd(&g_done[b], 1u);
        s_isLast = (prev == NCHUNK - 1) ? 1u : 0u;
    }
    __syncthreads();
    if (!s_isLast) return;

    if (t == 0) g_done[b] = 0;   // reset for next graph replay (deterministic)
    __threadfence();

    // per-batch softmax scalars (warp 0, one lane per chunk)
    if (t < 32) {
        const float mc = g_pm[b][t];
        const float lc = g_pl[b][t];
        const float cc = g_pcnt[b][t];
        float Mg = mc;
        #pragma unroll
        for (int o = 16; o > 0; o >>= 1)
            Mg = fmaxf(Mg, __shfl_xor_sync(0xffffffffu, Mg, o));
        const float ec = __expf(mc - Mg);
        float L = lc * ec, C = cc;
        #pragma unroll
        for (int o = 16; o > 0; o >>= 1) {
            L += __shfl_xor_sync(0xffffffffu, L, o);
            C += __shfl_xor_sync(0xffffffffu, C, o);
        }
        s_wc[t] = ec / L;
        if (t == 0) s_invcnt = 1.f / (C + 1e-6f);
    }
    __syncthreads();

    // thread t reduces its 4 columns over 32 chunks (coalesced float4 stream, L2-hot)
    float rs[4] = {0.f, 0.f, 0.f, 0.f};
    float rx[4] = {-BIGV, -BIGV, -BIGV, -BIGV};
    float rn[4] = { BIGV,  BIGV,  BIGV,  BIGV};
    float ra[4] = {0.f, 0.f, 0.f, 0.f};
    #pragma unroll 4
    for (int c = 0; c < NCHUNK; c++) {
        const float wc = s_wc[c];
        #pragma unroll
        for (int j = 0; j < 4; j++) {
            const float4 p = g_part[b][c][c0 + j];
            rs[j] += p.x;
            rx[j]  = fmaxf(rx[j], p.y);
            rn[j]  = fminf(rn[j], p.z);
            ra[j] += p.w * wc;
        }
    }
    float* ob = out + (size_t)b * (4 * ND);
    const float4 o0 = make_float4(rs[0] * s_invcnt, rs[1] * s_invcnt,
                                  rs[2] * s_invcnt, rs[3] * s_invcnt);
    *reinterpret_cast<float4*>(ob + c0)          = o0;
    *reinterpret_cast<float4*>(ob + ND + c0)     = make_float4(rx[0], rx[1], rx[2], rx[3]);
    *reinterpret_cast<float4*>(ob + 2 * ND + c0) = make_float4(rn[0], rn[1], rn[2], rn[3]);
    *reinterpret_cast<float4*>(ob + 3 * ND + c0) = make_float4(ra[0], ra[1], ra[2], ra[3]);
}

extern "C" void kernel_launch(void* const* d_in, const int* in_sizes, int n_in,
                              void* d_out, int out_size)
{
    const float* x  = (const float*)d_in[0];
    const int*   mk = (const int*)d_in[1];
    const float* w  = (const float*)d_in[2];
    float* out      = (float*)d_out;

    dim3 grid1(NCHUNK, NB);   // (32, 32) = 1024 CTAs, single fused kernel
    pool_fused<<<grid1, T1>>>(x, mk, w, out);
}

// round 10
// speedup vs baseline: 1.6033x; 1.6033x over previous
#include <cuda_runtime.h>
#include <math.h>

#define NB 32
#define NS 4096
#define ND 512
#define NCHUNK 32
#define ROWS_PER_CHUNK (NS / NCHUNK)        // 128
#define ROWS_PER_WARP  (ROWS_PER_CHUNK / 4) // 32
#define T1 128
#define BIGV 10000.0f

__device__ float g_psum[NB][NCHUNK][ND];
__device__ float g_pmax[NB][NCHUNK][ND];
__device__ float g_pmin[NB][NCHUNK][ND];
__device__ float g_pacc[NB][NCHUNK][ND];
__device__ float g_pm [NB][NCHUNK];
__device__ float g_pl [NB][NCHUNK];
__device__ float g_pcnt[NB][NCHUNK];

__device__ __forceinline__ float dot4(const float4& a, const float4& b) {
    return a.x * b.x + a.y * b.y + a.z * b.z + a.w * b.w;
}

__global__ __launch_bounds__(T1, 4) void pool_pass1(
    const float* __restrict__ x,
    const int* __restrict__ mask,   // 4-byte mask (int32 {0,1} or f32 {0.,1.}): nonzero-bits test exact
    const float* __restrict__ w)
{
    const int chunk = blockIdx.x;
    const int b     = blockIdx.y;
    const int t     = threadIdx.x;
    const int lane  = t & 31;
    const int wid   = t >> 5;            // warp owns 32 contiguous rows

    __shared__ int   s_list[4][ROWS_PER_WARP];
    __shared__ float s_m[4], s_l[4], s_cnt[4];
    __shared__ float s_mrg[2][4][ND];    // two planes, reused in two merge stages (16 KB)

    float4 w4[4];
    #pragma unroll
    for (int k = 0; k < 4; k++)
        w4[k] = *reinterpret_cast<const float4*>(w + k * 128 + lane * 4);

    float4 vsum[4], vmax[4], vmin[4], vacc[4];
    #pragma unroll
    for (int k = 0; k < 4; k++) {
        vsum[k] = make_float4(0.f, 0.f, 0.f, 0.f);
        vmax[k] = make_float4(-BIGV, -BIGV, -BIGV, -BIGV);
        vmin[k] = make_float4( BIGV,  BIGV,  BIGV,  BIGV);
        vacc[k] = make_float4(0.f, 0.f, 0.f, 0.f);
    }
    float m = -1e30f, l = 0.f;

    const int rowbase = chunk * ROWS_PER_CHUNK + wid * ROWS_PER_WARP;
    const float* xb = x + (size_t)b * NS * ND;

    // ---- compact 32 rows via ballot (coalesced mask load)
    const bool a = (mask[(size_t)b * NS + rowbase + lane] != 0);
    const unsigned bal = __ballot_sync(0xffffffffu, a);
    if (a) s_list[wid][__popc(bal & ((1u << lane) - 1u))] = lane;
    const int nact = __popc(bal);
    __syncwarp();

    // ---- main loop: 2 rows in flight, lazy max-rescale (uniform branch)
    int i = 0;
    for (; i + 2 <= nact; i += 2) {
        float4 v0[4], v1[4];
        {
            const float* p0 = xb + (size_t)(rowbase + s_list[wid][i])     * ND + lane * 4;
            const float* p1 = xb + (size_t)(rowbase + s_list[wid][i + 1]) * ND + lane * 4;
            #pragma unroll
            for (int k = 0; k < 4; k++) v0[k] = *reinterpret_cast<const float4*>(p0 + k * 128);
            #pragma unroll
            for (int k = 0; k < 4; k++) v1[k] = *reinterpret_cast<const float4*>(p1 + k * 128);
        }
        float d0 = dot4(v0[0], w4[0]) + dot4(v0[1], w4[1]) + dot4(v0[2], w4[2]) + dot4(v0[3], w4[3]);
        float d1 = dot4(v1[0], w4[0]) + dot4(v1[1], w4[1]) + dot4(v1[2], w4[2]) + dot4(v1[3], w4[3]);
        #pragma unroll
        for (int off = 16; off > 0; off >>= 1) {
            d0 += __shfl_xor_sync(0xffffffffu, d0, off);
            d1 += __shfl_xor_sync(0xffffffffu, d1, off);
        }

        // sum/max/min: unconditional
        #pragma unroll
        for (int k = 0; k < 4; k++) {
            float* S  = reinterpret_cast<float*>(&vsum[k]);
            float* Mx = reinterpret_cast<float*>(&vmax[k]);
            float* Mn = reinterpret_cast<float*>(&vmin[k]);
            #pragma unroll
            for (int c = 0; c < 4; c++) {
                const float x0 = reinterpret_cast<float*>(&v0[k])[c];
                const float x1 = reinterpret_cast<float*>(&v1[k])[c];
                S[c] += x0 + x1;
                Mx[c] = fmaxf(Mx[c], fmaxf(x0, x1));
                Mn[c] = fminf(Mn[c], fminf(x0, x1));
            }
        }

        // row 0: lazy rescale (d0 warp-uniform)
        if (d0 > m) {
            const float s = __expf(m - d0);
            l *= s;
            #pragma unroll
            for (int k = 0; k < 4; k++) {
                vacc[k].x *= s; vacc[k].y *= s; vacc[k].z *= s; vacc[k].w *= s;
            }
            m = d0;
        }
        {
            const float e0 = __expf(d0 - m);
            l += e0;
            #pragma unroll
            for (int k = 0; k < 4; k++) {
                vacc[k].x += e0 * v0[k].x; vacc[k].y += e0 * v0[k].y;
                vacc[k].z += e0 * v0[k].z; vacc[k].w += e0 * v0[k].w;
            }
        }
        // row 1
        if (d1 > m) {
            const float s = __expf(m - d1);
            l *= s;
            #pragma unroll
            for (int k = 0; k < 4; k++) {
                vacc[k].x *= s; vacc[k].y *= s; vacc[k].z *= s; vacc[k].w *= s;
            }
            m = d1;
        }
        {
            const float e1 = __expf(d1 - m);
            l += e1;
            #pragma unroll
            for (int k = 0; k < 4; k++) {
                vacc[k].x += e1 * v1[k].x; vacc[k].y += e1 * v1[k].y;
                vacc[k].z += e1 * v1[k].z; vacc[k].w += e1 * v1[k].w;
            }
        }
    }
    if (i < nact) {   // odd tail
        float4 v0[4];
        const float* p0 = xb + (size_t)(rowbase + s_list[wid][i]) * ND + lane * 4;
        #pragma unroll
        for (int k = 0; k < 4; k++) v0[k] = *reinterpret_cast<const float4*>(p0 + k * 128);
        float d0 = dot4(v0[0], w4[0]) + dot4(v0[1], w4[1]) + dot4(v0[2], w4[2]) + dot4(v0[3], w4[3]);
        #pragma unroll
        for (int off = 16; off > 0; off >>= 1)
            d0 += __shfl_xor_sync(0xffffffffu, d0, off);
        #pragma unroll
        for (int k = 0; k < 4; k++) {
            float* S  = reinterpret_cast<float*>(&vsum[k]);
            float* Mx = reinterpret_cast<float*>(&vmax[k]);
            float* Mn = reinterpret_cast<float*>(&vmin[k]);
            #pragma unroll
            for (int c = 0; c < 4; c++) {
                const float x0 = reinterpret_cast<float*>(&v0[k])[c];
                S[c] += x0;
                Mx[c] = fmaxf(Mx[c], x0);
                Mn[c] = fminf(Mn[c], x0);
            }
        }
        if (d0 > m) {
            const float s = __expf(m - d0);
            l *= s;
            #pragma unroll
            for (int k = 0; k < 4; k++) {
                vacc[k].x *= s; vacc[k].y *= s; vacc[k].z *= s; vacc[k].w *= s;
            }
            m = d0;
        }
        const float e0 = __expf(d0 - m);
        l += e0;
        #pragma unroll
        for (int k = 0; k < 4; k++) {
            vacc[k].x += e0 * v0[k].x; vacc[k].y += e0 * v0[k].y;
            vacc[k].z += e0 * v0[k].z; vacc[k].w += e0 * v0[k].w;
        }
    }

    // ---- two-stage merge across 4 warps (smem plane reuse)
    if (lane == 0) { s_m[wid] = m; s_cnt[wid] = (float)nact; }
    #pragma unroll
    for (int k = 0; k < 4; k++) {
        const int c = k * 128 + lane * 4;
        *reinterpret_cast<float4*>(&s_mrg[0][wid][c]) = vsum[k];
        *reinterpret_cast<float4*>(&s_mrg[1][wid][c]) = vmax[k];
    }
    __syncthreads();

    const float M  = fmaxf(fmaxf(s_m[0], s_m[1]), fmaxf(s_m[2], s_m[3]));
    const float sc = __expf(m - M);

    const int c0 = t * 4;
    {
        float4 osum = *reinterpret_cast<float4*>(&s_mrg[0][0][c0]);
        float4 omax = *reinterpret_cast<float4*>(&s_mrg[1][0][c0]);
        #pragma unroll
        for (int wi = 1; wi < 4; wi++) {
            const float4 q0 = *reinterpret_cast<float4*>(&s_mrg[0][wi][c0]);
            const float4 q1 = *reinterpret_cast<float4*>(&s_mrg[1][wi][c0]);
            osum.x += q0.x; osum.y += q0.y; osum.z += q0.z; osum.w += q0.w;
            omax.x = fmaxf(omax.x, q1.x); omax.y = fmaxf(omax.y, q1.y);
            omax.z = fmaxf(omax.z, q1.z); omax.w = fmaxf(omax.w, q1.w);
        }
        *reinterpret_cast<float4*>(&g_psum[b][chunk][c0]) = osum;
        *reinterpret_cast<float4*>(&g_pmax[b][chunk][c0]) = omax;
    }
    __syncthreads();   // protect plane reuse

    #pragma unroll
    for (int k = 0; k < 4; k++) {
        const int c = k * 128 + lane * 4;
        *reinterpret_cast<float4*>(&s_mrg[0][wid][c]) = vmin[k];
        float4 av = vacc[k];
        av.x *= sc; av.y *= sc; av.z *= sc; av.w *= sc;
        *reinterpret_cast<float4*>(&s_mrg[1][wid][c]) = av;
    }
    if (lane == 0) s_l[wid] = l * sc;
    __syncthreads();

    {
        float4 omin = *reinterpret_cast<float4*>(&s_mrg[0][0][c0]);
        float4 oacc = *reinterpret_cast<float4*>(&s_mrg[1][0][c0]);
        #pragma unroll
        for (int wi = 1; wi < 4; wi++) {
            const float4 q0 = *reinterpret_cast<float4*>(&s_mrg[0][wi][c0]);
            const float4 q1 = *reinterpret_cast<float4*>(&s_mrg[1][wi][c0]);
            omin.x = fminf(omin.x, q0.x); omin.y = fminf(omin.y, q0.y);
            omin.z = fminf(omin.z, q0.z); omin.w = fminf(omin.w, q0.w);
            oacc.x += q1.x; oacc.y += q1.y; oacc.z += q1.z; oacc.w += q1.w;
        }
        *reinterpret_cast<float4*>(&g_pmin[b][chunk][c0]) = omin;
        *reinterpret_cast<float4*>(&g_pacc[b][chunk][c0]) = oacc;
    }
    if (t == 0) {
        g_pm[b][chunk]   = M;
        g_pl[b][chunk]   = s_l[0] + s_l[1] + s_l[2] + s_l[3];
        g_pcnt[b][chunk] = s_cnt[0] + s_cnt[1] + s_cnt[2] + s_cnt[3];
    }
}

// pass2 (R7 version): grid (NB, 8); block = 64 columns × 8 chunk-slices;
// warp 0 precomputes per-batch normalized softmax weights once.
#define T2 512
#define COLS_PER_BLK 64
#define NSLICE 8
#define CHUNKS_PER_SLICE (NCHUNK / NSLICE)  // 4

__global__ __launch_bounds__(T2) void pool_pass2(float* __restrict__ out)
{
    const int b     = blockIdx.x;
    const int tid   = threadIdx.x;
    const int col   = blockIdx.y * COLS_PER_BLK + (tid & (COLS_PER_BLK - 1));
    const int slice = tid >> 6;

    __shared__ float s_wc[NCHUNK];   // exp(m_c - M) / L
    __shared__ float s_invcnt;
    __shared__ float s_sum[NSLICE][COLS_PER_BLK];
    __shared__ float s_max[NSLICE][COLS_PER_BLK];
    __shared__ float s_min[NSLICE][COLS_PER_BLK];
    __shared__ float s_acc[NSLICE][COLS_PER_BLK];

    if (tid < 32) {
        const float mc = g_pm[b][tid];
        const float lc = g_pl[b][tid];
        const float cc = g_pcnt[b][tid];
        float M = mc;
        #pragma unroll
        for (int off = 16; off > 0; off >>= 1)
            M = fmaxf(M, __shfl_xor_sync(0xffffffffu, M, off));
        const float ec = __expf(mc - M);
        float L = lc * ec, C = cc;
        #pragma unroll
        for (int off = 16; off > 0; off >>= 1) {
            L += __shfl_xor_sync(0xffffffffu, L, off);
            C += __shfl_xor_sync(0xffffffffu, C, off);
        }
        s_wc[tid] = ec / L;
        if (tid == 0) s_invcnt = 1.f / (C + 1e-6f);
    }
    __syncthreads();

    float sum = 0.f, mx = -BIGV, mn = BIGV, acc = 0.f;
    const int cbase = slice * CHUNKS_PER_SLICE;
    #pragma unroll
    for (int ii = 0; ii < CHUNKS_PER_SLICE; ii++) {
        const int c = cbase + ii;
        sum += g_psum[b][c][col];
        mx   = fmaxf(mx, g_pmax[b][c][col]);
        mn   = fminf(mn, g_pmin[b][c][col]);
        acc += g_pacc[b][c][col] * s_wc[c];
    }

    const int lc2 = tid & (COLS_PER_BLK - 1);
    s_sum[slice][lc2] = sum;
    s_max[slice][lc2] = mx;
    s_min[slice][lc2] = mn;
    s_acc[slice][lc2] = acc;
    __syncthreads();

    if (slice == 0) {
        #pragma unroll
        for (int s = 1; s < NSLICE; s++) {
            sum += s_sum[s][lc2];
            mx   = fmaxf(mx, s_max[s][lc2]);
            mn   = fminf(mn, s_min[s][lc2]);
            acc += s_acc[s][lc2];
        }
        float* ob = out + (size_t)b * (4 * ND);
        ob[col]          = sum * s_invcnt;
        ob[ND + col]     = mx;
        ob[2 * ND + col] = mn;
        ob[3 * ND + col] = acc;    // weights already normalized by 1/L
    }
}

extern "C" void kernel_launch(void* const* d_in, const int* in_sizes, int n_in,
                              void* d_out, int out_size)
{
    const float* x  = (const float*)d_in[0];
    const int*   mk = (const int*)d_in[1];
    const float* w  = (const float*)d_in[2];
    float* out      = (float*)d_out;

    dim3 grid1(NCHUNK, NB);   // (32, 32) = 1024 CTAs
    pool_pass1<<<grid1, T1>>>(x, mk, w);
    dim3 grid2(NB, ND / COLS_PER_BLK);   // (32, 8)
    pool_pass2<<<grid2, T2>>>(out);
}